// round 9
// baseline (speedup 1.0000x reference)
#include <cuda_runtime.h>
#include <cuda_bf16.h>
#include <cstdint>

#define M_ROWS   32768
#define DIM      256
#define KCODES   1024
#define MARGIN   0.6f
#define CHECK_CAP 8192

// Scratch (no cudaMalloc allowed)
__device__ int   g_indices[M_ROWS];
__device__ float g_cnorm[KCODES];
__device__ float g_partials[2048];
__device__ int   g_ncheck;
__device__ int   g_check[CHECK_CAP];
// Prepacked bf16 codebook in m16n8k16 B-fragment order, tile-major:
// [tile t 0..63][nbp 0..7][ks 0..1][lane 0..31] x uint4
//   t = chunk*8 + kt  (chunk: 128-code group, kt: 32-k group)
//   uint4 = { nb0.b0, nb0.b1, nb1.b0, nb1.b1 }, nb0 = 2*nbp, nb1 = 2*nbp+1
//   n = chunk*128 + nb*8 + (lane>>2); kb = kt*32 + ks*16 + 2*(lane&3)
//   b0 = bf16x2{B[n][kb], B[n][kb+1]}, b1 = bf16x2{B[n][kb+8], B[n][kb+9]}
__device__ uint4 g_bfrag[32768];   // 512 KB

// ---------------------------------------------------------------------------
// SMEM layout per CTA (64 rows):
//  A: bf16 fragment-order [mb 0..3][kstep 0..15][lane][4 regs] = 32 KB
//  B: 3 bufs x 8 KB fragment-order tiles                       = 24 KB
//  red: [64 rows][4] float4                                    = 4 KB
// ---------------------------------------------------------------------------
#define SM_A     0
#define SM_BF(b) (32768 + (b) * 8192)
#define SM_RED   57344
#define SM_TOTAL 61440

__device__ __forceinline__ uint32_t smem_u32(const void* p) {
    uint32_t a;
    asm("{ .reg .u64 t; cvta.to.shared.u64 t, %1; cvt.u32.u64 %0, t; }"
        : "=r"(a) : "l"(p));
    return a;
}
__device__ __forceinline__ void lds128(uint32_t* r, uint32_t addr) {
    asm volatile("ld.shared.v4.u32 {%0,%1,%2,%3}, [%4];"
                 : "=r"(r[0]), "=r"(r[1]), "=r"(r[2]), "=r"(r[3]) : "r"(addr));
}
__device__ __forceinline__ void sts32(uint32_t addr, uint32_t v) {
    asm volatile("st.shared.u32 [%0], %1;" :: "r"(addr), "r"(v) : "memory");
}
__device__ __forceinline__ void cp16(uint32_t dst, const void* src) {
    asm volatile("cp.async.cg.shared.global [%0], [%1], 16;"
                 :: "r"(dst), "l"(src) : "memory");
}
__device__ __forceinline__ void cp_commit() {
    asm volatile("cp.async.commit_group;" ::: "memory");
}
__device__ __forceinline__ void cp_wait1() {
    asm volatile("cp.async.wait_group 1;" ::: "memory");
}
__device__ __forceinline__ void cp_wait0() {
    asm volatile("cp.async.wait_group 0;" ::: "memory");
}

// bf16 m16n8k16 mma, fp32 accum
__device__ __forceinline__ void mma16816(float* d, const uint32_t* a,
                                         const uint32_t* b) {
    asm volatile(
        "mma.sync.aligned.m16n8k16.row.col.f32.bf16.bf16.f32 "
        "{%0,%1,%2,%3}, {%4,%5,%6,%7}, {%8,%9}, {%0,%1,%2,%3};"
        : "+f"(d[0]), "+f"(d[1]), "+f"(d[2]), "+f"(d[3])
        : "r"(a[0]), "r"(a[1]), "r"(a[2]), "r"(a[3]), "r"(b[0]), "r"(b[1]));
}

__device__ __forceinline__ uint32_t pk_bf16x2(float x, float y) {
    __nv_bfloat162 p;
    p.x = __float2bfloat16(x);
    p.y = __float2bfloat16(y);
    return *reinterpret_cast<uint32_t*>(&p);
}

__device__ __forceinline__ void upd2(float& m1, int& i1, float& m2, int& i2,
                                     float d, int c) {
    if (d < m1 || (d == m1 && c < i1)) { m2 = m1; i2 = i1; m1 = d; i1 = c; }
    else if (d < m2 || (d == m2 && c < i2)) { m2 = d; i2 = c; }
}
__device__ __forceinline__ void merge2(float& m1, int& i1, float& m2, int& i2,
                                       float om1, int oi1, float om2, int oi2) {
    if (om1 < m1 || (om1 == m1 && oi1 < i1)) {
        float c = m1; int ci = i1;
        m1 = om1; i1 = oi1;
        if (om2 < c || (om2 == c && oi2 < ci)) { m2 = om2; i2 = oi2; }
        else                                   { m2 = c;   i2 = ci;  }
    } else if (om1 < m2 || (om1 == m2 && oi1 < i2)) {
        m2 = om1; i2 = oi1;
    }
}

// ---------------------------------------------------------------------------
// Kernel 0: prepack codebook into bf16 B-fragment order (one shot, 512 KB)
// ---------------------------------------------------------------------------
__global__ void prepack_kernel(const float* __restrict__ cb) {
    int idx  = blockIdx.x * 256 + threadIdx.x;    // [0, 32768)
    int lane = idx & 31;
    int ks   = (idx >> 5) & 1;
    int nbp  = (idx >> 6) & 7;
    int kt   = (idx >> 9) & 7;
    int chunk = idx >> 12;
    int n0 = chunk * 128 + (2 * nbp) * 8 + (lane >> 2);
    int n1 = n0 + 8;
    int kb = kt * 32 + ks * 16 + 2 * (lane & 3);
    const float* r0 = cb + (size_t)n0 * DIM + kb;
    const float* r1 = cb + (size_t)n1 * DIM + kb;
    uint4 v;
    v.x = pk_bf16x2(r0[0], r0[1]);
    v.y = pk_bf16x2(r0[8], r0[9]);
    v.z = pk_bf16x2(r1[0], r1[1]);
    v.w = pk_bf16x2(r1[8], r1[9]);
    g_bfrag[idx] = v;
}

// ---------------------------------------------------------------------------
// Kernel 1: codebook norms + zero recheck counter
// ---------------------------------------------------------------------------
__global__ void cnorm_kernel(const float* __restrict__ codebook) {
    if (blockIdx.x == 0 && threadIdx.x == 0) g_ncheck = 0;
    int warp = (blockIdx.x * blockDim.x + threadIdx.x) >> 5;
    int lane = threadIdx.x & 31;
    if (warp >= KCODES) return;
    const float* row = codebook + (size_t)warp * DIM;
    float s = 0.f;
    #pragma unroll
    for (int i = 0; i < DIM / 32; ++i) { float v = row[lane + i * 32]; s += v * v; }
    #pragma unroll
    for (int o = 16; o; o >>= 1) s += __shfl_xor_sync(0xffffffffu, s, o);
    if (lane == 0) g_cnorm[warp] = s;
}

// ---------------------------------------------------------------------------
// Kernel 2: coarse bf16 distance GEMM + fused top-2 argmin + margin flags.
// Per CTA: 64 rows x 1024 codes, K=256. 2 CTAs/SM, 3-stage cp.async pipe.
// ---------------------------------------------------------------------------
__global__ __launch_bounds__(256, 2)
void argmin_bf16(const float* __restrict__ z, const float* __restrict__ cb) {
    extern __shared__ char sm[];
    const int tid  = threadIdx.x;
    const int lane = tid & 31;
    const int wid  = tid >> 5;
    const int wm   = wid >> 2;      // 0..1 : M group of 32 rows
    const int wn   = wid & 3;       // 0..3 : N group of 32 codes
    const int q    = lane & 3;
    const int rowBase = blockIdx.x * 64;
    const uint32_t sbase = smem_u32(sm);
    const char* bsrc = (const char*)g_bfrag;

    // cp.async: 8 KB tile = 512 x 16B; thread's 2 chunks, consumer order
    const uint32_t cpo0 = (uint32_t)tid * 16;
    const uint32_t cpo1 = (uint32_t)(256 + tid) * 16;

    // prefetch tiles 0 and 1
    cp16(sbase + SM_BF(0) + cpo0, bsrc + cpo0);
    cp16(sbase + SM_BF(0) + cpo1, bsrc + cpo1);
    cp_commit();
    cp16(sbase + SM_BF(1) + cpo0, bsrc + 8192 + cpo0);
    cp16(sbase + SM_BF(1) + cpo1, bsrc + 8192 + cpo1);
    cp_commit();

    // ---- A prologue: 64 z rows -> bf16 fragment-order smem ----
    // reg r: row += (r&1)*8, k += (r>>1)*8
    #pragma unroll
    for (int it = 0; it < 32; ++it) {
        int idx = it * 256 + tid;              // [0, 8192)
        int reg = idx & 3, l = (idx >> 2) & 31;
        int kstep = (idx >> 7) & 15, mb = idx >> 11;
        int row = mb * 16 + (l >> 2) + (reg & 1) * 8;
        int k   = kstep * 16 + 2 * (l & 3) + (reg >> 1) * 8;
        float2 v = *(const float2*)(z + (size_t)(rowBase + row) * DIM + k);
        sts32(sbase + SM_A + (uint32_t)(((mb * 16 + kstep) * 32 + l) * 16 + reg * 4),
              pk_bf16x2(v.x, v.y));
    }

    float tm1[4], tm2[4];
    int   ti1[4], ti2[4];
    #pragma unroll
    for (int s = 0; s < 4; ++s) {
        tm1[s] = 3.4e38f; tm2[s] = 3.4e38f;
        ti1[s] = 0x7fffffff; ti2[s] = 0x7fffffff;
    }

    float acc[2][4][4];
    #pragma unroll
    for (int mt = 0; mt < 2; ++mt)
        #pragma unroll
        for (int nt = 0; nt < 4; ++nt)
            #pragma unroll
            for (int e = 0; e < 4; ++e) acc[mt][nt][e] = 0.f;

    #pragma unroll 1
    for (int t = 0; t < 64; ++t) {             // 8 chunks x 8 k-tiles of 32
        if (t < 63) cp_wait1(); else cp_wait0();   // tile t resident
        __syncthreads();

        // prefetch tile t+2 (two tiles in flight)
        if (t < 62) {
            uint32_t dst = sbase + SM_BF((t + 2) % 3);
            uint32_t src = (uint32_t)(t + 2) * 8192;
            cp16(dst + cpo0, bsrc + src + cpo0);
            cp16(dst + cpo1, bsrc + src + cpo1);
            cp_commit();
        }

        const uint32_t bbuf = sbase + SM_BF(t % 3);
        const int kt = t & 7;
        #pragma unroll
        for (int ks = 0; ks < 2; ++ks) {
            uint32_t a[2][4], bq[2][4];
            #pragma unroll
            for (int mt = 0; mt < 2; ++mt) {
                int mb = wm * 2 + mt;
                lds128(a[mt], sbase + SM_A +
                       (uint32_t)(((mb * 16 + kt * 2 + ks) * 32 + lane) * 16));
            }
            #pragma unroll
            for (int pp = 0; pp < 2; ++pp) {
                int nbp = wn * 2 + pp;
                lds128(bq[pp], bbuf +
                       (uint32_t)(((nbp * 2 + ks) * 32 + lane) * 16));
            }
            #pragma unroll
            for (int mt = 0; mt < 2; ++mt)
                #pragma unroll
                for (int pp = 0; pp < 2; ++pp) {
                    mma16816(acc[mt][pp * 2 + 0], a[mt], &bq[pp][0]);
                    mma16816(acc[mt][pp * 2 + 1], a[mt], &bq[pp][2]);
                }
        }

        // chunk epilogue every 8 tiles
        if ((t & 7) == 7) {
            const int codeBase = (t >> 3) * 128;
            #pragma unroll
            for (int mt = 0; mt < 2; ++mt)
                #pragma unroll
                for (int nt = 0; nt < 4; ++nt) {
                    int col = codeBase + wn * 32 + nt * 8 + 2 * q;
                    float c0 = g_cnorm[col], c1 = g_cnorm[col + 1];
                    #pragma unroll
                    for (int hh = 0; hh < 2; ++hh) {
                        int s = mt * 2 + hh;
                        float d0 = fmaf(-2.f, acc[mt][nt][hh * 2 + 0], c0);
                        float d1 = fmaf(-2.f, acc[mt][nt][hh * 2 + 1], c1);
                        upd2(tm1[s], ti1[s], tm2[s], ti2[s], d0, col);
                        upd2(tm1[s], ti1[s], tm2[s], ti2[s], d1, col + 1);
                    }
                }
            #pragma unroll
            for (int mt = 0; mt < 2; ++mt)
                #pragma unroll
                for (int nt = 0; nt < 4; ++nt)
                    #pragma unroll
                    for (int e = 0; e < 4; ++e) acc[mt][nt][e] = 0.f;
        }
    }

    // ---- final reduce: quad shuffle, then across the 4 N-warps via SMEM ----
    float4* red = (float4*)(sm + SM_RED);   // [64 rows][4 wn]
    __syncthreads();
    #pragma unroll
    for (int s = 0; s < 4; ++s) {
        float m1 = tm1[s], m2 = tm2[s];
        int   i1 = ti1[s], i2 = ti2[s];
        #pragma unroll
        for (int off = 1; off <= 2; off <<= 1) {
            float om1 = __shfl_xor_sync(0xffffffffu, m1, off);
            int   oi1 = __shfl_xor_sync(0xffffffffu, i1, off);
            float om2 = __shfl_xor_sync(0xffffffffu, m2, off);
            int   oi2 = __shfl_xor_sync(0xffffffffu, i2, off);
            merge2(m1, i1, m2, i2, om1, oi1, om2, oi2);
        }
        if (q == 0) {
            int mt = s >> 1, hh = s & 1;
            int row = wm * 32 + mt * 16 + hh * 8 + (lane >> 2);
            red[row * 4 + wn] = make_float4(m1, __int_as_float(i1),
                                            m2, __int_as_float(i2));
        }
    }
    __syncthreads();

    if (tid < 64) {
        float4 p = red[tid * 4 + 0];
        float m1 = p.x, m2 = p.z;
        int   i1 = __float_as_int(p.y), i2 = __float_as_int(p.w);
        #pragma unroll
        for (int w = 1; w < 4; ++w) {
            float4 o = red[tid * 4 + w];
            merge2(m1, i1, m2, i2, o.x, __float_as_int(o.y),
                   o.z, __float_as_int(o.w));
        }
        int row = rowBase + tid;
        g_indices[row] = i1;
        if (m2 - m1 <= MARGIN) {             // coarse near-tie: exact recheck
            int slot = atomicAdd(&g_ncheck, 1);
            if (slot < CHECK_CAP) g_check[slot] = row;
        }
    }
}

// ---------------------------------------------------------------------------
// Kernel 3: FULL-ROW exact fp32 recheck of flagged rows.
// CTA: 8 warps, one flagged row per warp per pass; codebook streamed through
// smem in 32-code tiles; lane c handles code (tile*32 + c) end-to-end.
// ---------------------------------------------------------------------------
__global__ __launch_bounds__(256)
void recheck_kernel(const float* __restrict__ z, const float* __restrict__ cb) {
    __shared__ float s_e[32 * 258];          // stride 258: conflict-free-ish
    __shared__ float s_z[8][256];

    const int tid  = threadIdx.x;
    const int wid  = tid >> 5;
    const int lane = tid & 31;

    int n = g_ncheck; if (n > CHECK_CAP) n = CHECK_CAP;
    int passes = (n + 1023) >> 10;           // 128 CTAs x 8 warps = 1024/pass

    for (int p = 0; p < passes; ++p) {
        int e = p * 1024 + blockIdx.x * 8 + wid;
        bool act = (e < n);
        int row = act ? g_check[e] : 0;

        // load this warp's z row into smem (64 float4 per row)
        {
            const float4* src = (const float4*)(z + (size_t)row * DIM);
            ((float4*)s_z[wid])[lane]      = src[lane];
            ((float4*)s_z[wid])[lane + 32] = src[lane + 32];
        }

        float bm = 3.4e38f;
        int   bi = 0x7fffffff;

        for (int tb = 0; tb < 32; ++tb) {
            __syncthreads();
            // CTA loads 32 codes (32 KB) into padded smem
            #pragma unroll
            for (int i = tid; i < 2048; i += 256) {    // 2048 float4
                int c = i >> 6, d4 = (i & 63) * 4;
                float4 v = ((const float4*)(cb + (size_t)(tb * 32 + c) * DIM))[i & 63];
                float* dst = s_e + c * 258 + d4;
                dst[0] = v.x; dst[1] = v.y; dst[2] = v.z; dst[3] = v.w;
            }
            __syncthreads();

            // lane handles code tb*32 + lane, full 256-dim exact distance
            const float* ep = s_e + lane * 258;
            const float* zp = s_z[wid];
            float s = 0.f;
            #pragma unroll 8
            for (int j = 0; j < 128; ++j) {
                float2 ev = *(const float2*)(ep + 2 * j);
                float2 zv = *(const float2*)(zp + 2 * j);
                float dx = zv.x - ev.x, dy = zv.y - ev.y;
                s = fmaf(dx, dx, s);
                s = fmaf(dy, dy, s);
            }
            int code = tb * 32 + lane;
            if (s < bm) { bm = s; bi = code; }
        }

        // warp argmin reduce (lowest index on ties)
        #pragma unroll
        for (int o = 16; o; o >>= 1) {
            float ov = __shfl_xor_sync(0xffffffffu, bm, o);
            int   oi = __shfl_xor_sync(0xffffffffu, bi, o);
            if (ov < bm || (ov == bm && oi < bi)) { bm = ov; bi = oi; }
        }
        if (act && lane == 0) g_indices[row] = bi;
    }
}

// ---------------------------------------------------------------------------
// Kernel 4: copy z_e, gather z_q (z_q_st == z_q), partial loss sums
// ---------------------------------------------------------------------------
__global__ void gather_kernel(const float* __restrict__ z,
                              const float* __restrict__ cb,
                              float* __restrict__ out) {
    const int TOTAL4 = (M_ROWS * DIM) / 4;
    float* __restrict__ out_ze = out;
    float* __restrict__ out_zq = out + (size_t)M_ROWS * DIM + 1;

    float lsum = 0.f;
    int stride = gridDim.x * blockDim.x;
    for (int t = blockIdx.x * blockDim.x + threadIdx.x; t < TOTAL4; t += stride) {
        float4 ze = ((const float4*)z)[t];
        ((float4*)out_ze)[t] = ze;
        int row = t >> 6;
        int idx = g_indices[row];
        float4 qv = ((const float4*)cb)[(size_t)idx * 64 + (t & 63)];
        float dx = qv.x - ze.x, dy = qv.y - ze.y;
        float dz = qv.z - ze.z, dw = qv.w - ze.w;
        lsum += dx * dx + dy * dy + dz * dz + dw * dw;
        size_t b = (size_t)t * 4;
        out_zq[b + 0] = qv.x; out_zq[b + 1] = qv.y;
        out_zq[b + 2] = qv.z; out_zq[b + 3] = qv.w;
    }

    __shared__ float red[256];
    red[threadIdx.x] = lsum;
    __syncthreads();
    #pragma unroll
    for (int s = 128; s; s >>= 1) {
        if (threadIdx.x < s) red[threadIdx.x] += red[threadIdx.x + s];
        __syncthreads();
    }
    if (threadIdx.x == 0) g_partials[blockIdx.x] = red[0];
}

// ---------------------------------------------------------------------------
// Kernel 5: deterministic final loss
// ---------------------------------------------------------------------------
__global__ void finalize_kernel(float* __restrict__ out) {
    __shared__ float red[1024];
    int t = threadIdx.x;
    red[t] = g_partials[t] + g_partials[t + 1024];
    __syncthreads();
    #pragma unroll
    for (int s = 512; s; s >>= 1) {
        if (t < s) red[t] += red[t + s];
        __syncthreads();
    }
    if (t == 0)
        out[(size_t)M_ROWS * DIM] = 2.0f * red[0] / (float)(M_ROWS * DIM);
}

// ---------------------------------------------------------------------------
extern "C" void kernel_launch(void* const* d_in, const int* in_sizes, int n_in,
                              void* d_out, int out_size) {
    const float* z  = (const float*)d_in[0];
    const float* cb = (const float*)d_in[1];
    float* out = (float*)d_out;

    cudaFuncSetAttribute(argmin_bf16,
                         cudaFuncAttributeMaxDynamicSharedMemorySize, SM_TOTAL);

    prepack_kernel <<<128, 256>>>(cb);
    cnorm_kernel   <<<KCODES / 8, 256>>>(cb);
    argmin_bf16    <<<M_ROWS / 64, 256, SM_TOTAL>>>(z, cb);
    recheck_kernel <<<128, 256>>>(z, cb);
    gather_kernel  <<<2048, 256>>>(z, cb, out);
    finalize_kernel<<<1, 1024>>>(out);
}

// round 10
// speedup vs baseline: 1.4052x; 1.4052x over previous
#include <cuda_runtime.h>
#include <cuda_bf16.h>
#include <cstdint>

#define M_ROWS   32768
#define DIM      256
#define KCODES   1024
#define MARGIN_B 0.7f      // stage-1 bf16 near-tie margin
#define MARGIN_T 0.25f     // stage-2 tf32 near-tie margin
#define CAP1     32768
#define CAP2     8192

// Scratch (no cudaMalloc allowed)
__device__ int   g_indices[M_ROWS];
__device__ float g_cnorm[KCODES];
__device__ float g_partials[2048];
__device__ int   g_ncheck1;
__device__ int   g_check1[CAP1];
__device__ int   g_ncheck2;
__device__ int4  g_check2[CAP2];
// bf16 B-fragments, tile-major (stage 1):
// [t 0..63][nbp 0..7][ks 0..1][lane] uint4 = {nb0.b0,nb0.b1,nb1.b0,nb1.b1}
__device__ uint4  g_bfrag16[32768];   // 512 KB
// fp32(tf32) B-fragments (stage 2): [p 0..63][ks 0..31][lane] float4
__device__ float4 g_bfrag32[65536];   // 1 MB

// ---------------- stage-1 smem ----------------
#define SM1_A     0
#define SM1_BF(b) (32768 + (b) * 8192)
#define SM1_RED   57344
#define SM1_TOTAL 61440
// ---------------- stage-2 smem ----------------
#define SM2_A     0
#define SM2_BF(b) (65536 + (b) * 16384)
#define SM2_RED   98304
#define SM2_TOTAL 102400

__device__ __forceinline__ uint32_t smem_u32(const void* p) {
    uint32_t a;
    asm("{ .reg .u64 t; cvta.to.shared.u64 t, %1; cvt.u32.u64 %0, t; }"
        : "=r"(a) : "l"(p));
    return a;
}
__device__ __forceinline__ void lds128(uint32_t* r, uint32_t addr) {
    asm volatile("ld.shared.v4.u32 {%0,%1,%2,%3}, [%4];"
                 : "=r"(r[0]), "=r"(r[1]), "=r"(r[2]), "=r"(r[3]) : "r"(addr));
}
__device__ __forceinline__ void sts32(uint32_t addr, uint32_t v) {
    asm volatile("st.shared.u32 [%0], %1;" :: "r"(addr), "r"(v) : "memory");
}
__device__ __forceinline__ void cp16(uint32_t dst, const void* src) {
    asm volatile("cp.async.cg.shared.global [%0], [%1], 16;"
                 :: "r"(dst), "l"(src) : "memory");
}
__device__ __forceinline__ void cp_commit() {
    asm volatile("cp.async.commit_group;" ::: "memory");
}
__device__ __forceinline__ void cp_wait1() {
    asm volatile("cp.async.wait_group 1;" ::: "memory");
}
__device__ __forceinline__ void cp_wait0() {
    asm volatile("cp.async.wait_group 0;" ::: "memory");
}

__device__ __forceinline__ void mma_bf16(float* d, const uint32_t* a,
                                         const uint32_t* b) {
    asm volatile(
        "mma.sync.aligned.m16n8k16.row.col.f32.bf16.bf16.f32 "
        "{%0,%1,%2,%3}, {%4,%5,%6,%7}, {%8,%9}, {%0,%1,%2,%3};"
        : "+f"(d[0]), "+f"(d[1]), "+f"(d[2]), "+f"(d[3])
        : "r"(a[0]), "r"(a[1]), "r"(a[2]), "r"(a[3]), "r"(b[0]), "r"(b[1]));
}
__device__ __forceinline__ void mma_tf32(float* d, const uint32_t* a,
                                         const uint32_t* b) {
    asm volatile(
        "mma.sync.aligned.m16n8k8.row.col.f32.tf32.tf32.f32 "
        "{%0,%1,%2,%3}, {%4,%5,%6,%7}, {%8,%9}, {%0,%1,%2,%3};"
        : "+f"(d[0]), "+f"(d[1]), "+f"(d[2]), "+f"(d[3])
        : "r"(a[0]), "r"(a[1]), "r"(a[2]), "r"(a[3]), "r"(b[0]), "r"(b[1]));
}

__device__ __forceinline__ uint32_t pk_bf16x2(float x, float y) {
    __nv_bfloat162 p;
    p.x = __float2bfloat16(x);
    p.y = __float2bfloat16(y);
    return *reinterpret_cast<uint32_t*>(&p);
}

__device__ __forceinline__ void upd2(float& m1, int& i1, float& m2, int& i2,
                                     float d, int c) {
    if (d < m1 || (d == m1 && c < i1)) { m2 = m1; i2 = i1; m1 = d; i1 = c; }
    else if (d < m2 || (d == m2 && c < i2)) { m2 = d; i2 = c; }
}
__device__ __forceinline__ void merge2(float& m1, int& i1, float& m2, int& i2,
                                       float om1, int oi1, float om2, int oi2) {
    if (om1 < m1 || (om1 == m1 && oi1 < i1)) {
        float c = m1; int ci = i1;
        m1 = om1; i1 = oi1;
        if (om2 < c || (om2 == c && oi2 < ci)) { m2 = om2; i2 = oi2; }
        else                                   { m2 = c;   i2 = ci;  }
    } else if (om1 < m2 || (om1 == m2 && oi1 < i2)) {
        m2 = om1; i2 = oi1;
    }
}

// ---------------------------------------------------------------------------
// Prepack kernels (one shot)
// ---------------------------------------------------------------------------
__global__ void prepack16_kernel(const float* __restrict__ cb) {
    int idx  = blockIdx.x * 256 + threadIdx.x;    // [0, 32768)
    int lane = idx & 31;
    int ks   = (idx >> 5) & 1;
    int nbp  = (idx >> 6) & 7;
    int kt   = (idx >> 9) & 7;
    int chunk = idx >> 12;
    int n0 = chunk * 128 + (2 * nbp) * 8 + (lane >> 2);
    int n1 = n0 + 8;
    int kb = kt * 32 + ks * 16 + 2 * (lane & 3);
    const float* r0 = cb + (size_t)n0 * DIM + kb;
    const float* r1 = cb + (size_t)n1 * DIM + kb;
    uint4 v;
    v.x = pk_bf16x2(r0[0], r0[1]);
    v.y = pk_bf16x2(r0[8], r0[9]);
    v.z = pk_bf16x2(r1[0], r1[1]);
    v.w = pk_bf16x2(r1[8], r1[9]);
    g_bfrag16[idx] = v;
}

__global__ void prepack32_kernel(const float* __restrict__ cb) {
    int idx = blockIdx.x * 256 + threadIdx.x;     // (p*32 + ks)*32 + lane
    int lane = idx & 31;
    int ks   = (idx >> 5) & 31;
    int p    = idx >> 10;
    int k  = ks * 8 + (lane & 3);
    int n0 = (2 * p) * 8 + (lane >> 2);
    int n1 = n0 + 8;
    float4 v;
    v.x = cb[(size_t)n0 * DIM + k];
    v.y = cb[(size_t)n0 * DIM + k + 4];
    v.z = cb[(size_t)n1 * DIM + k];
    v.w = cb[(size_t)n1 * DIM + k + 4];
    g_bfrag32[idx] = v;
}

// ---------------------------------------------------------------------------
// Kernel 1: codebook norms + zero both queue counters
// ---------------------------------------------------------------------------
__global__ void cnorm_kernel(const float* __restrict__ codebook) {
    if (blockIdx.x == 0 && threadIdx.x == 0) { g_ncheck1 = 0; g_ncheck2 = 0; }
    int warp = (blockIdx.x * blockDim.x + threadIdx.x) >> 5;
    int lane = threadIdx.x & 31;
    if (warp >= KCODES) return;
    const float* row = codebook + (size_t)warp * DIM;
    float s = 0.f;
    #pragma unroll
    for (int i = 0; i < DIM / 32; ++i) { float v = row[lane + i * 32]; s += v * v; }
    #pragma unroll
    for (int o = 16; o; o >>= 1) s += __shfl_xor_sync(0xffffffffu, s, o);
    if (lane == 0) g_cnorm[warp] = s;
}

// ---------------------------------------------------------------------------
// Stage 1: coarse bf16 distance GEMM + top-2 argmin; flag gap<=MARGIN_B rows.
// ---------------------------------------------------------------------------
__global__ __launch_bounds__(256, 2)
void argmin_bf16(const float* __restrict__ z, const float* __restrict__ cb) {
    extern __shared__ char sm[];
    const int tid  = threadIdx.x;
    const int lane = tid & 31;
    const int wid  = tid >> 5;
    const int wm   = wid >> 2;
    const int wn   = wid & 3;
    const int q    = lane & 3;
    const int rowBase = blockIdx.x * 64;
    const uint32_t sbase = smem_u32(sm);
    const char* bsrc = (const char*)g_bfrag16;

    const uint32_t cpo0 = (uint32_t)tid * 16;
    const uint32_t cpo1 = (uint32_t)(256 + tid) * 16;

    cp16(sbase + SM1_BF(0) + cpo0, bsrc + cpo0);
    cp16(sbase + SM1_BF(0) + cpo1, bsrc + cpo1);
    cp_commit();
    cp16(sbase + SM1_BF(1) + cpo0, bsrc + 8192 + cpo0);
    cp16(sbase + SM1_BF(1) + cpo1, bsrc + 8192 + cpo1);
    cp_commit();

    // A prologue: 64 z rows -> bf16 fragment-order smem
    #pragma unroll
    for (int it = 0; it < 32; ++it) {
        int idx = it * 256 + tid;
        int reg = idx & 3, l = (idx >> 2) & 31;
        int kstep = (idx >> 7) & 15, mb = idx >> 11;
        int row = mb * 16 + (l >> 2) + (reg & 1) * 8;
        int k   = kstep * 16 + 2 * (l & 3) + (reg >> 1) * 8;
        float2 v = *(const float2*)(z + (size_t)(rowBase + row) * DIM + k);
        sts32(sbase + SM1_A + (uint32_t)(((mb * 16 + kstep) * 32 + l) * 16 + reg * 4),
              pk_bf16x2(v.x, v.y));
    }

    float tm1[4], tm2[4];
    int   ti1[4], ti2[4];
    #pragma unroll
    for (int s = 0; s < 4; ++s) {
        tm1[s] = 3.4e38f; tm2[s] = 3.4e38f;
        ti1[s] = 0x7fffffff; ti2[s] = 0x7fffffff;
    }
    float acc[2][4][4];
    #pragma unroll
    for (int mt = 0; mt < 2; ++mt)
        #pragma unroll
        for (int nt = 0; nt < 4; ++nt)
            #pragma unroll
            for (int e = 0; e < 4; ++e) acc[mt][nt][e] = 0.f;

    #pragma unroll 1
    for (int t = 0; t < 64; ++t) {
        if (t < 63) cp_wait1(); else cp_wait0();
        __syncthreads();

        if (t < 62) {
            uint32_t dst = sbase + SM1_BF((t + 2) % 3);
            uint32_t src = (uint32_t)(t + 2) * 8192;
            cp16(dst + cpo0, bsrc + src + cpo0);
            cp16(dst + cpo1, bsrc + src + cpo1);
            cp_commit();
        }

        const uint32_t bbuf = sbase + SM1_BF(t % 3);
        const int kt = t & 7;
        #pragma unroll
        for (int ks = 0; ks < 2; ++ks) {
            uint32_t a[2][4], bq[2][4];
            #pragma unroll
            for (int mt = 0; mt < 2; ++mt) {
                int mb = wm * 2 + mt;
                lds128(a[mt], sbase + SM1_A +
                       (uint32_t)(((mb * 16 + kt * 2 + ks) * 32 + lane) * 16));
            }
            #pragma unroll
            for (int pp = 0; pp < 2; ++pp) {
                int nbp = wn * 2 + pp;
                lds128(bq[pp], bbuf +
                       (uint32_t)(((nbp * 2 + ks) * 32 + lane) * 16));
            }
            #pragma unroll
            for (int mt = 0; mt < 2; ++mt)
                #pragma unroll
                for (int pp = 0; pp < 2; ++pp) {
                    mma_bf16(acc[mt][pp * 2 + 0], a[mt], &bq[pp][0]);
                    mma_bf16(acc[mt][pp * 2 + 1], a[mt], &bq[pp][2]);
                }
        }

        if ((t & 7) == 7) {
            const int codeBase = (t >> 3) * 128;
            #pragma unroll
            for (int mt = 0; mt < 2; ++mt)
                #pragma unroll
                for (int nt = 0; nt < 4; ++nt) {
                    int col = codeBase + wn * 32 + nt * 8 + 2 * q;
                    float c0 = g_cnorm[col], c1 = g_cnorm[col + 1];
                    #pragma unroll
                    for (int hh = 0; hh < 2; ++hh) {
                        int s = mt * 2 + hh;
                        float d0 = fmaf(-2.f, acc[mt][nt][hh * 2 + 0], c0);
                        float d1 = fmaf(-2.f, acc[mt][nt][hh * 2 + 1], c1);
                        upd2(tm1[s], ti1[s], tm2[s], ti2[s], d0, col);
                        upd2(tm1[s], ti1[s], tm2[s], ti2[s], d1, col + 1);
                    }
                }
            #pragma unroll
            for (int mt = 0; mt < 2; ++mt)
                #pragma unroll
                for (int nt = 0; nt < 4; ++nt)
                    #pragma unroll
                    for (int e = 0; e < 4; ++e) acc[mt][nt][e] = 0.f;
        }
    }

    float4* red = (float4*)(sm + SM1_RED);
    __syncthreads();
    #pragma unroll
    for (int s = 0; s < 4; ++s) {
        float m1 = tm1[s], m2 = tm2[s];
        int   i1 = ti1[s], i2 = ti2[s];
        #pragma unroll
        for (int off = 1; off <= 2; off <<= 1) {
            float om1 = __shfl_xor_sync(0xffffffffu, m1, off);
            int   oi1 = __shfl_xor_sync(0xffffffffu, i1, off);
            float om2 = __shfl_xor_sync(0xffffffffu, m2, off);
            int   oi2 = __shfl_xor_sync(0xffffffffu, i2, off);
            merge2(m1, i1, m2, i2, om1, oi1, om2, oi2);
        }
        if (q == 0) {
            int mt = s >> 1, hh = s & 1;
            int row = wm * 32 + mt * 16 + hh * 8 + (lane >> 2);
            red[row * 4 + wn] = make_float4(m1, __int_as_float(i1),
                                            m2, __int_as_float(i2));
        }
    }
    __syncthreads();

    if (tid < 64) {
        float4 p = red[tid * 4 + 0];
        float m1 = p.x, m2 = p.z;
        int   i1 = __float_as_int(p.y), i2 = __float_as_int(p.w);
        #pragma unroll
        for (int w = 1; w < 4; ++w) {
            float4 o = red[tid * 4 + w];
            merge2(m1, i1, m2, i2, o.x, __float_as_int(o.y),
                   o.z, __float_as_int(o.w));
        }
        int row = rowBase + tid;
        g_indices[row] = i1;
        if (m2 - m1 <= MARGIN_B) {
            int slot = atomicAdd(&g_ncheck1, 1);
            if (slot < CAP1) g_check1[slot] = row;   // CAP1 == M_ROWS: no drop
        }
    }
}

// ---------------------------------------------------------------------------
// Stage 2: tf32 full-row refine of flagged rows (indirect 64-row gather).
// Fixed grid 512 CTAs; CTAs with no work exit immediately.
// ---------------------------------------------------------------------------
__global__ __launch_bounds__(256, 2)
void refine_tf32(const float* __restrict__ z) {
    int n = g_ncheck1; if (n > CAP1) n = CAP1;
    const int base = blockIdx.x * 64;
    if (base >= n) return;

    extern __shared__ char sm[];
    __shared__ int s_rows[64];
    __shared__ int s_act[64];

    const int tid  = threadIdx.x;
    const int lane = tid & 31;
    const int wid  = tid >> 5;
    const int wm   = wid >> 2;
    const int wn   = wid & 3;
    const int q    = lane & 3;
    const uint32_t sbase = smem_u32(sm);
    const char* bsrc = (const char*)g_bfrag32;

    if (tid < 64) {
        int e = base + tid;
        int a = (e < n) ? 1 : 0;
        s_act[tid]  = a;
        s_rows[tid] = a ? g_check1[e] : g_check1[base];
    }
    __syncthreads();

    uint32_t cpd[4], cps[4];
    #pragma unroll
    for (int it = 0; it < 4; ++it) {
        int idx = it * 256 + tid;
        cpd[it] = (uint32_t)idx * 16;
        int pl = idx >> 7, ka = (idx >> 5) & 3, ls = idx & 31;
        cps[it] = (uint32_t)((pl * 32 + ka) * 512 + ls * 16);
    }
    #pragma unroll
    for (int it = 0; it < 4; ++it)
        cp16(sbase + SM2_BF(0) + cpd[it], bsrc + cps[it]);
    cp_commit();

    // A prologue: gathered rows -> fp32 fragment-order smem
    #pragma unroll
    for (int it = 0; it < 16; ++it) {
        int idx = it * 256 + tid;
        int r = idx >> 6, c = (idx & 63) * 4;
        float4 v = *(const float4*)(z + (size_t)s_rows[r] * DIM + c);
        int mb = r >> 4, kstep = c >> 3;
        int fbase = ((r >> 3) & 1) + 2 * ((c >> 2) & 1);
        uint32_t lbase = sbase + SM2_A + (uint32_t)((mb * 32 + kstep) * 512
                       + ((r & 7) * 4) * 16 + fbase * 4);
        sts32(lbase +  0, __float_as_uint(v.x));
        sts32(lbase + 16, __float_as_uint(v.y));
        sts32(lbase + 32, __float_as_uint(v.z));
        sts32(lbase + 48, __float_as_uint(v.w));
    }

    float tm1[4], tm2[4];
    int   ti1[4], ti2[4];
    #pragma unroll
    for (int s = 0; s < 4; ++s) {
        tm1[s] = 3.4e38f; tm2[s] = 3.4e38f;
        ti1[s] = 0x7fffffff; ti2[s] = 0x7fffffff;
    }
    float acc[2][4][4];
    #pragma unroll
    for (int mt = 0; mt < 2; ++mt)
        #pragma unroll
        for (int nt = 0; nt < 4; ++nt)
            #pragma unroll
            for (int e = 0; e < 4; ++e) acc[mt][nt][e] = 0.f;

    #pragma unroll 1
    for (int t = 0; t < 64; ++t) {
        const int buf = t & 1;
        cp_wait0();
        __syncthreads();

        if (t < 63) {
            int tn = t + 1;
            uint32_t tbase = (uint32_t)(((tn >> 3) * 256 + (tn & 7) * 4) * 512);
            #pragma unroll
            for (int it = 0; it < 4; ++it)
                cp16(sbase + SM2_BF(buf ^ 1) + cpd[it], bsrc + tbase + cps[it]);
            cp_commit();
        }

        const int kt = t & 7;
        #pragma unroll
        for (int ksl = 0; ksl < 4; ++ksl) {
            uint32_t a[2][4], bq[2][4];
            #pragma unroll
            for (int mt = 0; mt < 2; ++mt) {
                int mb = wm * 2 + mt, kstep = kt * 4 + ksl;
                lds128(a[mt], sbase + SM2_A +
                       (uint32_t)((mb * 32 + kstep) * 512 + lane * 16));
            }
            #pragma unroll
            for (int pp = 0; pp < 2; ++pp) {
                int pl = wn * 2 + pp;
                lds128(bq[pp], sbase + SM2_BF(buf) +
                       (uint32_t)(((pl * 4 + ksl) * 32 + lane) * 16));
            }
            #pragma unroll
            for (int mt = 0; mt < 2; ++mt)
                #pragma unroll
                for (int pp = 0; pp < 2; ++pp) {
                    mma_tf32(acc[mt][pp * 2 + 0], a[mt], &bq[pp][0]);
                    mma_tf32(acc[mt][pp * 2 + 1], a[mt], &bq[pp][2]);
                }
        }

        if ((t & 7) == 7) {
            const int codeBase = (t >> 3) * 128;
            #pragma unroll
            for (int mt = 0; mt < 2; ++mt)
                #pragma unroll
                for (int nt = 0; nt < 4; ++nt) {
                    int col = codeBase + wn * 32 + nt * 8 + 2 * q;
                    float c0 = g_cnorm[col], c1 = g_cnorm[col + 1];
                    #pragma unroll
                    for (int hh = 0; hh < 2; ++hh) {
                        int s = mt * 2 + hh;
                        float d0 = fmaf(-2.f, acc[mt][nt][hh * 2 + 0], c0);
                        float d1 = fmaf(-2.f, acc[mt][nt][hh * 2 + 1], c1);
                        upd2(tm1[s], ti1[s], tm2[s], ti2[s], d0, col);
                        upd2(tm1[s], ti1[s], tm2[s], ti2[s], d1, col + 1);
                    }
                }
            #pragma unroll
            for (int mt = 0; mt < 2; ++mt)
                #pragma unroll
                for (int nt = 0; nt < 4; ++nt)
                    #pragma unroll
                    for (int e = 0; e < 4; ++e) acc[mt][nt][e] = 0.f;
        }
    }

    float4* red = (float4*)(sm + SM2_RED);
    __syncthreads();
    #pragma unroll
    for (int s = 0; s < 4; ++s) {
        float m1 = tm1[s], m2 = tm2[s];
        int   i1 = ti1[s], i2 = ti2[s];
        #pragma unroll
        for (int off = 1; off <= 2; off <<= 1) {
            float om1 = __shfl_xor_sync(0xffffffffu, m1, off);
            int   oi1 = __shfl_xor_sync(0xffffffffu, i1, off);
            float om2 = __shfl_xor_sync(0xffffffffu, m2, off);
            int   oi2 = __shfl_xor_sync(0xffffffffu, i2, off);
            merge2(m1, i1, m2, i2, om1, oi1, om2, oi2);
        }
        if (q == 0) {
            int mt = s >> 1, hh = s & 1;
            int row = wm * 32 + mt * 16 + hh * 8 + (lane >> 2);
            red[row * 4 + wn] = make_float4(m1, __int_as_float(i1),
                                            m2, __int_as_float(i2));
        }
    }
    __syncthreads();

    if (tid < 64 && s_act[tid]) {
        float4 p = red[tid * 4 + 0];
        float m1 = p.x, m2 = p.z;
        int   i1 = __float_as_int(p.y), i2 = __float_as_int(p.w);
        #pragma unroll
        for (int w = 1; w < 4; ++w) {
            float4 o = red[tid * 4 + w];
            merge2(m1, i1, m2, i2, o.x, __float_as_int(o.y),
                   o.z, __float_as_int(o.w));
        }
        int row = s_rows[tid];
        g_indices[row] = i1;
        if (m2 - m1 <= MARGIN_T) {
            int slot = atomicAdd(&g_ncheck2, 1);
            if (slot < CAP2) g_check2[slot] = make_int4(row, i1, i2, 0);
        }
    }
}

// ---------------------------------------------------------------------------
// Stage 3: exact fp32 recheck of tf32 near-ties (one warp per entry)
// ---------------------------------------------------------------------------
__global__ void recheck_kernel(const float* __restrict__ z,
                               const float* __restrict__ cb) {
    int nw = (gridDim.x * blockDim.x) >> 5;
    int w = (blockIdx.x * blockDim.x + threadIdx.x) >> 5;
    int lane = threadIdx.x & 31;
    int n = g_ncheck2; if (n > CAP2) n = CAP2;
    for (int e = w; e < n; e += nw) {
        int4 ent = g_check2[e];
        const float* zr = z  + (size_t)ent.x * DIM;
        const float* e1 = cb + (size_t)ent.y * DIM;
        const float* e2 = cb + (size_t)ent.z * DIM;
        float d1 = 0.f, d2 = 0.f;
        for (int i = lane; i < DIM; i += 32) {
            float zv = zr[i];
            float a = zv - e1[i]; d1 += a * a;
            float b = zv - e2[i]; d2 += b * b;
        }
        #pragma unroll
        for (int o = 16; o; o >>= 1) {
            d1 += __shfl_xor_sync(0xffffffffu, d1, o);
            d2 += __shfl_xor_sync(0xffffffffu, d2, o);
        }
        if (lane == 0) {
            int best = (d1 < d2) ? ent.y : ((d2 < d1) ? ent.z
                        : (ent.y < ent.z ? ent.y : ent.z));
            g_indices[ent.x] = best;
        }
    }
}

// ---------------------------------------------------------------------------
// Kernel: copy z_e, gather z_q, partial loss sums
// ---------------------------------------------------------------------------
__global__ void gather_kernel(const float* __restrict__ z,
                              const float* __restrict__ cb,
                              float* __restrict__ out) {
    const int TOTAL4 = (M_ROWS * DIM) / 4;
    float* __restrict__ out_ze = out;
    float* __restrict__ out_zq = out + (size_t)M_ROWS * DIM + 1;

    float lsum = 0.f;
    int stride = gridDim.x * blockDim.x;
    for (int t = blockIdx.x * blockDim.x + threadIdx.x; t < TOTAL4; t += stride) {
        float4 ze = ((const float4*)z)[t];
        ((float4*)out_ze)[t] = ze;
        int row = t >> 6;
        int idx = g_indices[row];
        float4 qv = ((const float4*)cb)[(size_t)idx * 64 + (t & 63)];
        float dx = qv.x - ze.x, dy = qv.y - ze.y;
        float dz = qv.z - ze.z, dw = qv.w - ze.w;
        lsum += dx * dx + dy * dy + dz * dz + dw * dw;
        size_t b = (size_t)t * 4;
        out_zq[b + 0] = qv.x; out_zq[b + 1] = qv.y;
        out_zq[b + 2] = qv.z; out_zq[b + 3] = qv.w;
    }

    __shared__ float red[256];
    red[threadIdx.x] = lsum;
    __syncthreads();
    #pragma unroll
    for (int s = 128; s; s >>= 1) {
        if (threadIdx.x < s) red[threadIdx.x] += red[threadIdx.x + s];
        __syncthreads();
    }
    if (threadIdx.x == 0) g_partials[blockIdx.x] = red[0];
}

// ---------------------------------------------------------------------------
// Final loss
// ---------------------------------------------------------------------------
__global__ void finalize_kernel(float* __restrict__ out) {
    __shared__ float red[1024];
    int t = threadIdx.x;
    red[t] = g_partials[t] + g_partials[t + 1024];
    __syncthreads();
    #pragma unroll
    for (int s = 512; s; s >>= 1) {
        if (t < s) red[t] += red[t + s];
        __syncthreads();
    }
    if (t == 0)
        out[(size_t)M_ROWS * DIM] = 2.0f * red[0] / (float)(M_ROWS * DIM);
}

// ---------------------------------------------------------------------------
extern "C" void kernel_launch(void* const* d_in, const int* in_sizes, int n_in,
                              void* d_out, int out_size) {
    const float* z  = (const float*)d_in[0];
    const float* cb = (const float*)d_in[1];
    float* out = (float*)d_out;

    cudaFuncSetAttribute(argmin_bf16,
                         cudaFuncAttributeMaxDynamicSharedMemorySize, SM1_TOTAL);
    cudaFuncSetAttribute(refine_tf32,
                         cudaFuncAttributeMaxDynamicSharedMemorySize, SM2_TOTAL);

    prepack16_kernel<<<128, 256>>>(cb);
    prepack32_kernel<<<256, 256>>>(cb);
    cnorm_kernel    <<<KCODES / 8, 256>>>(cb);
    argmin_bf16     <<<M_ROWS / 64, 256, SM1_TOTAL>>>(z, cb);
    refine_tf32     <<<512, 256, SM2_TOTAL>>>(z);
    recheck_kernel  <<<64, 256>>>(z, cb);
    gather_kernel   <<<2048, 256>>>(z, cb, out);
    finalize_kernel <<<1, 1024>>>(out);
}

// round 12
// speedup vs baseline: 1.7360x; 1.2354x over previous
#include <cuda_runtime.h>
#include <cuda_bf16.h>
#include <cstdint>

#define M_ROWS   32768
#define DIM      256
#define KCODES   1024
#define MARGIN   0.3f
#define CHECK_CAP 32768

// Scratch (no cudaMalloc allowed)
__device__ int   g_indices[M_ROWS];
__device__ float g_cnorm[KCODES];
__device__ float g_partials[2048];
__device__ int   g_ncheck;
__device__ int4  g_check[CHECK_CAP];
// Prepacked bf16 codebook in m16n8k16 B-fragment order, tile-major:
// [tile t 0..63][nbp 0..7][ks 0..1][lane 0..31] x uint4  (validated R9/R10)
// warp wn's per-tile slice = contiguous 1KB at (t*8 + wn)*1024
__device__ uint4  g_bfrag16[32768];   // 512 KB

// ---------------------------------------------------------------------------
// SMEM per CTA: A_hi 32KB | A_lo 32KB | B 8 warps x 3 bufs x 1KB | red 8KB
// ---------------------------------------------------------------------------
#define SM_AHI   0
#define SM_ALO   32768
#define SM_B     65536
#define SM_RED   90112
#define SM_TOTAL 98304      // R12 fix: red needs 64*8*16 = 8KB (was 4KB OOB)

__device__ __forceinline__ uint32_t smem_u32(const void* p) {
    uint32_t a;
    asm("{ .reg .u64 t; cvta.to.shared.u64 t, %1; cvt.u32.u64 %0, t; }"
        : "=r"(a) : "l"(p));
    return a;
}
__device__ __forceinline__ void lds128(uint32_t* r, uint32_t addr) {
    asm volatile("ld.shared.v4.u32 {%0,%1,%2,%3}, [%4];"
                 : "=r"(r[0]), "=r"(r[1]), "=r"(r[2]), "=r"(r[3]) : "r"(addr));
}
__device__ __forceinline__ void sts32(uint32_t addr, uint32_t v) {
    asm volatile("st.shared.u32 [%0], %1;" :: "r"(addr), "r"(v) : "memory");
}
__device__ __forceinline__ void cp16(uint32_t dst, const void* src) {
    asm volatile("cp.async.cg.shared.global [%0], [%1], 16;"
                 :: "r"(dst), "l"(src) : "memory");
}
__device__ __forceinline__ void cp_commit() {
    asm volatile("cp.async.commit_group;" ::: "memory");
}
__device__ __forceinline__ void cp_wait1() {
    asm volatile("cp.async.wait_group 1;" ::: "memory");
}
__device__ __forceinline__ void cp_wait0() {
    asm volatile("cp.async.wait_group 0;" ::: "memory");
}

__device__ __forceinline__ void mma_bf16(float* d, const uint32_t* a,
                                         const uint32_t* b) {
    asm volatile(
        "mma.sync.aligned.m16n8k16.row.col.f32.bf16.bf16.f32 "
        "{%0,%1,%2,%3}, {%4,%5,%6,%7}, {%8,%9}, {%0,%1,%2,%3};"
        : "+f"(d[0]), "+f"(d[1]), "+f"(d[2]), "+f"(d[3])
        : "r"(a[0]), "r"(a[1]), "r"(a[2]), "r"(a[3]), "r"(b[0]), "r"(b[1]));
}

__device__ __forceinline__ uint32_t pk_bf16x2(float x, float y) {
    __nv_bfloat162 p;
    p.x = __float2bfloat16(x);
    p.y = __float2bfloat16(y);
    return *reinterpret_cast<uint32_t*>(&p);
}

__device__ __forceinline__ void upd2(float& m1, int& i1, float& m2, int& i2,
                                     float d, int c) {
    if (d < m1 || (d == m1 && c < i1)) { m2 = m1; i2 = i1; m1 = d; i1 = c; }
    else if (d < m2 || (d == m2 && c < i2)) { m2 = d; i2 = c; }
}
__device__ __forceinline__ void merge2(float& m1, int& i1, float& m2, int& i2,
                                       float om1, int oi1, float om2, int oi2) {
    if (om1 < m1 || (om1 == m1 && oi1 < i1)) {
        float c = m1; int ci = i1;
        m1 = om1; i1 = oi1;
        if (om2 < c || (om2 == c && oi2 < ci)) { m2 = om2; i2 = oi2; }
        else                                   { m2 = c;   i2 = ci;  }
    } else if (om1 < m2 || (om1 == m2 && oi1 < i2)) {
        m2 = om1; i2 = oi1;
    }
}

// ---------------------------------------------------------------------------
// Kernel 0: prepack codebook into bf16 B-fragment order (one shot, 512 KB)
// ---------------------------------------------------------------------------
__global__ void prepack16_kernel(const float* __restrict__ cb) {
    int idx  = blockIdx.x * 256 + threadIdx.x;    // [0, 32768)
    int lane = idx & 31;
    int ks   = (idx >> 5) & 1;
    int nbp  = (idx >> 6) & 7;
    int kt   = (idx >> 9) & 7;
    int chunk = idx >> 12;
    int n0 = chunk * 128 + (2 * nbp) * 8 + (lane >> 2);
    int n1 = n0 + 8;
    int kb = kt * 32 + ks * 16 + 2 * (lane & 3);
    const float* r0 = cb + (size_t)n0 * DIM + kb;
    const float* r1 = cb + (size_t)n1 * DIM + kb;
    uint4 v;
    v.x = pk_bf16x2(r0[0], r0[1]);
    v.y = pk_bf16x2(r0[8], r0[9]);
    v.z = pk_bf16x2(r1[0], r1[1]);
    v.w = pk_bf16x2(r1[8], r1[9]);
    g_bfrag16[idx] = v;
}

// ---------------------------------------------------------------------------
// Kernel 1: codebook norms + zero recheck counter
// ---------------------------------------------------------------------------
__global__ void cnorm_kernel(const float* __restrict__ codebook) {
    if (blockIdx.x == 0 && threadIdx.x == 0) g_ncheck = 0;
    int warp = (blockIdx.x * blockDim.x + threadIdx.x) >> 5;
    int lane = threadIdx.x & 31;
    if (warp >= KCODES) return;
    const float* row = codebook + (size_t)warp * DIM;
    float s = 0.f;
    #pragma unroll
    for (int i = 0; i < DIM / 32; ++i) { float v = row[lane + i * 32]; s += v * v; }
    #pragma unroll
    for (int o = 16; o; o >>= 1) s += __shfl_xor_sync(0xffffffffu, s, o);
    if (lane == 0) g_cnorm[warp] = s;
}

// ---------------------------------------------------------------------------
// Kernel 2: 2-term split-bf16 distance GEMM (A = hi+lo exact, B bf16) with
// fused top-2 argmin. Per CTA: 64 rows x 1024 codes. Warp wn owns ALL rows x
// its 16-code slice per chunk; B slices are warp-private (cp.async + syncwarp,
// NO CTA barrier in the mainloop). dist noise sigma ~0.036; MARGIN=0.3 flags
// near-ties for the exact pair recheck.
// ---------------------------------------------------------------------------
__global__ __launch_bounds__(256, 2)
void argmin_mma2(const float* __restrict__ z, const float* __restrict__ cb) {
    extern __shared__ char sm[];
    const int tid  = threadIdx.x;
    const int lane = tid & 31;
    const int wn   = tid >> 5;           // 0..7 : code-slice owner
    const int q    = lane & 3;
    const int rowBase = blockIdx.x * 64;
    const uint32_t sbase = smem_u32(sm);
    const char* bsrc = (const char*)g_bfrag16;

    // per-warp private B: 3 bufs x 1KB
    const uint32_t myB = sbase + SM_B + (uint32_t)wn * 3072;
    const uint32_t co0 = (uint32_t)lane * 16;
    const uint32_t co1 = co0 + 512;

    // prefetch tiles 0,1 into bufs 0,1 (warp-private groups)
    {
        const char* s0 = bsrc + (0 * 8 + wn) * 1024;
        cp16(myB + 0 * 1024 + co0, s0 + co0);
        cp16(myB + 0 * 1024 + co1, s0 + co1);
        cp_commit();
        const char* s1 = bsrc + (1 * 8 + wn) * 1024;
        cp16(myB + 1 * 1024 + co0, s1 + co0);
        cp16(myB + 1 * 1024 + co1, s1 + co1);
        cp_commit();
    }

    // ---- A prologue: 64 z rows -> hi/lo bf16 fragment-order smem ----
    #pragma unroll
    for (int it = 0; it < 32; ++it) {
        int idx = it * 256 + tid;              // [0, 8192)
        int reg = idx & 3, l = (idx >> 2) & 31;
        int kstep = (idx >> 7) & 15, mb = idx >> 11;   // mb 0..3
        int row = mb * 16 + (l >> 2) + (reg & 1) * 8;
        int k   = kstep * 16 + 2 * (l & 3) + (reg >> 1) * 8;
        float2 v = *(const float2*)(z + (size_t)(rowBase + row) * DIM + k);
        __nv_bfloat16 hx = __float2bfloat16(v.x);
        __nv_bfloat16 hy = __float2bfloat16(v.y);
        float lx = v.x - __bfloat162float(hx);
        float ly = v.y - __bfloat162float(hy);
        uint32_t off = (uint32_t)(((mb * 16 + kstep) * 32 + l) * 16 + reg * 4);
        __nv_bfloat162 hp; hp.x = hx; hp.y = hy;
        sts32(sbase + SM_AHI + off, *reinterpret_cast<uint32_t*>(&hp));
        sts32(sbase + SM_ALO + off, pk_bf16x2(lx, ly));
    }
    __syncthreads();                           // A visible to all; only CTA
                                               // barrier before the mainloop
    float tm1[8], tm2[8];
    int   ti1[8], ti2[8];
    #pragma unroll
    for (int s = 0; s < 8; ++s) {
        tm1[s] = 3.4e38f; tm2[s] = 3.4e38f;
        ti1[s] = 0x7fffffff; ti2[s] = 0x7fffffff;
    }

    float acc[4][2][4];
    #pragma unroll
    for (int mt = 0; mt < 4; ++mt)
        #pragma unroll
        for (int nt = 0; nt < 2; ++nt)
            #pragma unroll
            for (int e = 0; e < 4; ++e) acc[mt][nt][e] = 0.f;

    #pragma unroll 1
    for (int t = 0; t < 64; ++t) {             // 8 chunks x 8 k-tiles of 32
        if (t < 63) cp_wait1(); else cp_wait0();   // R12 fix: drain tail tile
        __syncwarp();                          // publish within warp

        if (t + 2 < 64) {                      // prefetch t+2 (warp-private)
            const char* s2 = bsrc + ((t + 2) * 8 + wn) * 1024;
            uint32_t d2 = myB + (uint32_t)((t + 2) % 3) * 1024;
            cp16(d2 + co0, s2 + co0);
            cp16(d2 + co1, s2 + co1);
            cp_commit();
        }

        const uint32_t bbuf = myB + (uint32_t)(t % 3) * 1024;
        const int kt = t & 7;
        #pragma unroll
        for (int ks = 0; ks < 2; ++ks) {
            uint32_t bq[4];
            lds128(bq, bbuf + (uint32_t)ks * 512 + co0);
            #pragma unroll
            for (int mt = 0; mt < 4; ++mt) {
                uint32_t aoff = (uint32_t)(((mt * 16 + kt * 2 + ks) * 32 + lane) * 16);
                uint32_t ah[4], al[4];
                lds128(ah, sbase + SM_AHI + aoff);
                mma_bf16(acc[mt][0], ah, &bq[0]);
                mma_bf16(acc[mt][1], ah, &bq[2]);
                lds128(al, sbase + SM_ALO + aoff);
                mma_bf16(acc[mt][0], al, &bq[0]);
                mma_bf16(acc[mt][1], al, &bq[2]);
            }
        }

        // chunk epilogue every 8 tiles
        if ((t & 7) == 7) {
            const int codeBase = (t >> 3) * 128;
            #pragma unroll
            for (int mt = 0; mt < 4; ++mt)
                #pragma unroll
                for (int nt = 0; nt < 2; ++nt) {
                    int col = codeBase + wn * 16 + nt * 8 + 2 * q;
                    float c0 = g_cnorm[col], c1 = g_cnorm[col + 1];
                    #pragma unroll
                    for (int hh = 0; hh < 2; ++hh) {
                        int s = mt * 2 + hh;
                        float d0 = fmaf(-2.f, acc[mt][nt][hh * 2 + 0], c0);
                        float d1 = fmaf(-2.f, acc[mt][nt][hh * 2 + 1], c1);
                        upd2(tm1[s], ti1[s], tm2[s], ti2[s], d0, col);
                        upd2(tm1[s], ti1[s], tm2[s], ti2[s], d1, col + 1);
                    }
                }
            #pragma unroll
            for (int mt = 0; mt < 4; ++mt)
                #pragma unroll
                for (int nt = 0; nt < 2; ++nt)
                    #pragma unroll
                    for (int e = 0; e < 4; ++e) acc[mt][nt][e] = 0.f;
        }
    }

    // ---- final reduce: quad shuffle, then across the 8 wn warps via SMEM ----
    float4* red = (float4*)(sm + SM_RED);      // [64 rows][8 wn] = 8KB
    #pragma unroll
    for (int s = 0; s < 8; ++s) {
        float m1 = tm1[s], m2 = tm2[s];
        int   i1 = ti1[s], i2 = ti2[s];
        #pragma unroll
        for (int off = 1; off <= 2; off <<= 1) {
            float om1 = __shfl_xor_sync(0xffffffffu, m1, off);
            int   oi1 = __shfl_xor_sync(0xffffffffu, i1, off);
            float om2 = __shfl_xor_sync(0xffffffffu, m2, off);
            int   oi2 = __shfl_xor_sync(0xffffffffu, i2, off);
            merge2(m1, i1, m2, i2, om1, oi1, om2, oi2);
        }
        if (q == 0) {
            int mt = s >> 1, hh = s & 1;
            int row = mt * 16 + hh * 8 + (lane >> 2);
            red[row * 8 + wn] = make_float4(m1, __int_as_float(i1),
                                            m2, __int_as_float(i2));
        }
    }
    __syncthreads();

    if (tid < 64) {
        float4 p = red[tid * 8 + 0];
        float m1 = p.x, m2 = p.z;
        int   i1 = __float_as_int(p.y), i2 = __float_as_int(p.w);
        #pragma unroll
        for (int w = 1; w < 8; ++w) {
            float4 o = red[tid * 8 + w];
            merge2(m1, i1, m2, i2, o.x, __float_as_int(o.y),
                   o.z, __float_as_int(o.w));
        }
        int row = rowBase + tid;
        g_indices[row] = i1;
        if (m2 - m1 <= MARGIN) {
            int slot = atomicAdd(&g_ncheck, 1);
            if (slot < CHECK_CAP) g_check[slot] = make_int4(row, i1, i2, 0);
        }
    }
}

// ---------------------------------------------------------------------------
// Kernel 3: exact fp32 pair recheck of flagged rows (one warp per entry)
// ---------------------------------------------------------------------------
__global__ void recheck_kernel(const float* __restrict__ z,
                               const float* __restrict__ cb) {
    int nw = (gridDim.x * blockDim.x) >> 5;
    int w = (blockIdx.x * blockDim.x + threadIdx.x) >> 5;
    int lane = threadIdx.x & 31;
    int n = g_ncheck; if (n > CHECK_CAP) n = CHECK_CAP;
    for (int e = w; e < n; e += nw) {
        int4 ent = g_check[e];
        const float* zr = z  + (size_t)ent.x * DIM;
        const float* e1 = cb + (size_t)ent.y * DIM;
        const float* e2 = cb + (size_t)ent.z * DIM;
        float d1 = 0.f, d2 = 0.f;
        for (int i = lane; i < DIM; i += 32) {
            float zv = zr[i];
            float a = zv - e1[i]; d1 += a * a;
            float b = zv - e2[i]; d2 += b * b;
        }
        #pragma unroll
        for (int o = 16; o; o >>= 1) {
            d1 += __shfl_xor_sync(0xffffffffu, d1, o);
            d2 += __shfl_xor_sync(0xffffffffu, d2, o);
        }
        if (lane == 0) {
            int best = (d1 < d2) ? ent.y : ((d2 < d1) ? ent.z
                        : (ent.y < ent.z ? ent.y : ent.z));
            g_indices[ent.x] = best;
        }
    }
}

// ---------------------------------------------------------------------------
// Kernel 4: copy z_e, gather z_q (z_q_st == z_q), partial loss sums
// ---------------------------------------------------------------------------
__global__ void gather_kernel(const float* __restrict__ z,
                              const float* __restrict__ cb,
                              float* __restrict__ out) {
    const int TOTAL4 = (M_ROWS * DIM) / 4;
    float* __restrict__ out_ze = out;
    float* __restrict__ out_zq = out + (size_t)M_ROWS * DIM + 1;

    float lsum = 0.f;
    int stride = gridDim.x * blockDim.x;
    for (int t = blockIdx.x * blockDim.x + threadIdx.x; t < TOTAL4; t += stride) {
        float4 ze = ((const float4*)z)[t];
        ((float4*)out_ze)[t] = ze;
        int row = t >> 6;
        int idx = g_indices[row];
        float4 qv = ((const float4*)cb)[(size_t)idx * 64 + (t & 63)];
        float dx = qv.x - ze.x, dy = qv.y - ze.y;
        float dz = qv.z - ze.z, dw = qv.w - ze.w;
        lsum += dx * dx + dy * dy + dz * dz + dw * dw;
        size_t b = (size_t)t * 4;
        out_zq[b + 0] = qv.x; out_zq[b + 1] = qv.y;
        out_zq[b + 2] = qv.z; out_zq[b + 3] = qv.w;
    }

    __shared__ float red[256];
    red[threadIdx.x] = lsum;
    __syncthreads();
    #pragma unroll
    for (int s = 128; s; s >>= 1) {
        if (threadIdx.x < s) red[threadIdx.x] += red[threadIdx.x + s];
        __syncthreads();
    }
    if (threadIdx.x == 0) g_partials[blockIdx.x] = red[0];
}

// ---------------------------------------------------------------------------
// Kernel 5: deterministic final loss
// ---------------------------------------------------------------------------
__global__ void finalize_kernel(float* __restrict__ out) {
    __shared__ float red[1024];
    int t = threadIdx.x;
    red[t] = g_partials[t] + g_partials[t + 1024];
    __syncthreads();
    #pragma unroll
    for (int s = 512; s; s >>= 1) {
        if (t < s) red[t] += red[t + s];
        __syncthreads();
    }
    if (t == 0)
        out[(size_t)M_ROWS * DIM] = 2.0f * red[0] / (float)(M_ROWS * DIM);
}

// ---------------------------------------------------------------------------
extern "C" void kernel_launch(void* const* d_in, const int* in_sizes, int n_in,
                              void* d_out, int out_size) {
    const float* z  = (const float*)d_in[0];
    const float* cb = (const float*)d_in[1];
    float* out = (float*)d_out;

    cudaFuncSetAttribute(argmin_mma2,
                         cudaFuncAttributeMaxDynamicSharedMemorySize, SM_TOTAL);

    prepack16_kernel<<<128, 256>>>(cb);
    cnorm_kernel    <<<KCODES / 8, 256>>>(cb);
    argmin_mma2     <<<M_ROWS / 64, 256, SM_TOTAL>>>(z, cb);
    recheck_kernel  <<<64, 256>>>(z, cb);
    gather_kernel   <<<2048, 256>>>(z, cb, out);
    finalize_kernel <<<1, 1024>>>(out);
}